// round 9
// baseline (speedup 1.0000x reference)
#include <cuda_runtime.h>

#define Hh 128
#define NS 18
#define SLOTS 10                 // warp-slots per CTA (1 sample per warp)
#define NTHREADS (SLOTS * 32)

typedef unsigned long long u64;

// ---- packed fp32x2 helpers (sm_103a) --------------------------------------
__device__ __forceinline__ u64 ffma2(u64 a, u64 b, u64 c) {
    u64 d;
    asm("fma.rn.f32x2 %0, %1, %2, %3;" : "=l"(d) : "l"(a), "l"(b), "l"(c));
    return d;
}
__device__ __forceinline__ u64 splat2(float w) {
    u64 d; unsigned ui = __float_as_uint(w);
    asm("mov.b64 %0, {%1, %1};" : "=l"(d) : "r"(ui));
    return d;
}
__device__ __forceinline__ void unpack2(u64 v, float& lo, float& hi) {
    unsigned a, b;
    asm("mov.b64 {%0, %1}, %2;" : "=r"(a), "=r"(b) : "l"(v));
    lo = __uint_as_float(a); hi = __uint_as_float(b);
}

// ---------------------------------------------------------------------------
// Truncated multivariate Taylor jet over monomials (normalized coefficients):
//  0:1  1:X 2:Y 3:T  4:X2 5:XY 6:Y2 7:XT 8:YT
//  9:X3 10:X2Y 11:XY2 12:Y3 13:X2T 14:Y2T  15:X4 16:X2Y2 17:Y4
// ---------------------------------------------------------------------------
__device__ __forceinline__ void tanh_jet(const float* __restrict__ u,
                                         float* __restrict__ o)
{
    const float t  = tanhf(u[0]);
    const float s  = 1.f - t * t;           // T1
    const float T2 = -t * s;
    const float T3 = (2.f * t * t - s) * s * (1.f / 3.f);
    const float T4 = (2.f * s - t * t) * t * s * (1.f / 3.f);

    const float a1 = u[1], a2 = u[2], a3 = u[3];
    const float b1 = u[4], b2 = u[5], b3 = u[6], b4 = u[7], b5 = u[8];
    const float c1 = u[9], c2 = u[10], c3 = u[11], c4 = u[12], c5 = u[13], c6 = u[14];
    const float a11 = a1 * a1, a22 = a2 * a2, a12 = a1 * a2;

    o[0] = t;
    o[1] = s * a1;
    o[2] = s * a2;
    o[3] = s * a3;
    o[4] = s * b1 + T2 * a11;
    o[5] = s * b2 + T2 * (2.f * a12);
    o[6] = s * b3 + T2 * a22;
    o[7] = s * b4 + T2 * (2.f * a1 * a3);
    o[8] = s * b5 + T2 * (2.f * a2 * a3);
    o[9]  = s * c1 + T2 * (2.f * a1 * b1)             + T3 * (a11 * a1);
    o[10] = s * c2 + T2 * (2.f * (a1 * b2 + a2 * b1)) + T3 * (3.f * a11 * a2);
    o[11] = s * c3 + T2 * (2.f * (a1 * b3 + a2 * b2)) + T3 * (3.f * a1 * a22);
    o[12] = s * c4 + T2 * (2.f * a2 * b3)             + T3 * (a22 * a2);
    o[13] = s * c5 + T2 * (2.f * (a1 * b4 + a3 * b1)) + T3 * (3.f * a11 * a3);
    o[14] = s * c6 + T2 * (2.f * (a2 * b5 + a3 * b3)) + T3 * (3.f * a22 * a3);
    o[15] = s * u[15] + T2 * (2.f * a1 * c1 + b1 * b1)
                      + T3 * (3.f * a11 * b1)
                      + T4 * (a11 * a11);
    o[16] = s * u[16] + T2 * (2.f * (a1 * c3 + a2 * c2 + b1 * b3) + b2 * b2)
                      + T3 * (3.f * (a11 * b3 + a22 * b1) + 6.f * a12 * b2)
                      + T4 * (6.f * a11 * a22);
    o[17] = s * u[17] + T2 * (2.f * a2 * c4 + b3 * b3)
                      + T3 * (3.f * a22 * b3)
                      + T4 * (a22 * a22);
}

// SoA jet chunk layout per slot: 4 float4 arrays (streams 0-15) + float2 (16,17)
__device__ __forceinline__ void store_jets(float4* __restrict__ J4,
                                           float2* __restrict__ J2,
                                           int j, const float* __restrict__ o)
{
    J4[0 * Hh + j] = make_float4(o[0],  o[1],  o[2],  o[3]);
    J4[1 * Hh + j] = make_float4(o[4],  o[5],  o[6],  o[7]);
    J4[2 * Hh + j] = make_float4(o[8],  o[9],  o[10], o[11]);
    J4[3 * Hh + j] = make_float4(o[12], o[13], o[14], o[15]);
    J2[j] = make_float2(o[16], o[17]);
}

// 4-neuron matvec with packed f32x2 FMAs. Weights interleaved float4:
// Wq[i*32+c] = (W[i][c], W[i][c+32], W[i][c+64], W[i][c+96]).
__device__ __forceinline__ void matvec4(const float4* __restrict__ Wq,
                                        const float4* __restrict__ J4,
                                        const float2* __restrict__ J2,
                                        int jj, u64* __restrict__ acc)
{
#pragma unroll
    for (int s = 0; s < 36; ++s) acc[s] = 0ull;
#pragma unroll 4
    for (int i = 0; i < Hh; ++i) {
        const ulonglong2 q0 = *(const ulonglong2*)(J4 + 0 * Hh + i);
        const ulonglong2 q1 = *(const ulonglong2*)(J4 + 1 * Hh + i);
        const ulonglong2 q2 = *(const ulonglong2*)(J4 + 2 * Hh + i);
        const ulonglong2 q3 = *(const ulonglong2*)(J4 + 3 * Hh + i);
        const u64 h8 = *(const u64*)(J2 + i);
        const float4 w = Wq[i * 32 + jj];
        const u64 w0 = splat2(w.x);
        const u64 w1 = splat2(w.y);
        const u64 w2 = splat2(w.z);
        const u64 w3 = splat2(w.w);

        acc[0]  = ffma2(w0, q0.x, acc[0]);
        acc[1]  = ffma2(w0, q0.y, acc[1]);
        acc[2]  = ffma2(w0, q1.x, acc[2]);
        acc[3]  = ffma2(w0, q1.y, acc[3]);
        acc[4]  = ffma2(w0, q2.x, acc[4]);
        acc[5]  = ffma2(w0, q2.y, acc[5]);
        acc[6]  = ffma2(w0, q3.x, acc[6]);
        acc[7]  = ffma2(w0, q3.y, acc[7]);
        acc[8]  = ffma2(w0, h8,   acc[8]);

        acc[9]  = ffma2(w1, q0.x, acc[9]);
        acc[10] = ffma2(w1, q0.y, acc[10]);
        acc[11] = ffma2(w1, q1.x, acc[11]);
        acc[12] = ffma2(w1, q1.y, acc[12]);
        acc[13] = ffma2(w1, q2.x, acc[13]);
        acc[14] = ffma2(w1, q2.y, acc[14]);
        acc[15] = ffma2(w1, q3.x, acc[15]);
        acc[16] = ffma2(w1, q3.y, acc[16]);
        acc[17] = ffma2(w1, h8,   acc[17]);

        acc[18] = ffma2(w2, q0.x, acc[18]);
        acc[19] = ffma2(w2, q0.y, acc[19]);
        acc[20] = ffma2(w2, q1.x, acc[20]);
        acc[21] = ffma2(w2, q1.y, acc[21]);
        acc[22] = ffma2(w2, q2.x, acc[22]);
        acc[23] = ffma2(w2, q2.y, acc[23]);
        acc[24] = ffma2(w2, q3.x, acc[24]);
        acc[25] = ffma2(w2, q3.y, acc[25]);
        acc[26] = ffma2(w2, h8,   acc[26]);

        acc[27] = ffma2(w3, q0.x, acc[27]);
        acc[28] = ffma2(w3, q0.y, acc[28]);
        acc[29] = ffma2(w3, q1.x, acc[29]);
        acc[30] = ffma2(w3, q1.y, acc[30]);
        acc[31] = ffma2(w3, q2.x, acc[31]);
        acc[32] = ffma2(w3, q2.y, acc[32]);
        acc[33] = ffma2(w3, q3.x, acc[33]);
        acc[34] = ffma2(w3, q3.y, acc[34]);
        acc[35] = ffma2(w3, h8,   acc[35]);
    }
}

__global__ void __launch_bounds__(NTHREADS, 1)
hydro_kernel(const float* __restrict__ x,
             const float* __restrict__ W1, const float* __restrict__ b1,
             const float* __restrict__ W2, const float* __restrict__ b2,
             const float* __restrict__ W3, const float* __restrict__ b3,
             const float* __restrict__ W4, const float* __restrict__ b4,
             const float* __restrict__ nup,
             float* __restrict__ out, int N)
{
    extern __shared__ float sm[];
    float4* Wq2 = (float4*)sm;                       // Hh*32 float4 (64KB)
    float4* Wq3 = Wq2 + Hh * 32;                     // Hh*32 float4 (64KB)
    float4* jets4 = (float4*)(Wq3 + Hh * 32);        // SLOTS*4*Hh float4
    float2* jets2 = (float2*)(jets4 + SLOTS * 4 * Hh);  // SLOTS*Hh float2
    float*  vecs  = (float*)(jets2 + SLOTS * Hh);    // 7*Hh floats

    float* w1s = vecs;             // 3*Hh (x,y,t rows)
    float* b1s = vecs + 3 * Hh;
    float* b2s = vecs + 4 * Hh;
    float* b3s = vecs + 5 * Hh;
    float* w4s = vecs + 6 * Hh;

    const int tid  = threadIdx.x;
    const int slot = tid >> 5;
    const int jj   = tid & 31;

    for (int k = tid; k < Hh * 32; k += NTHREADS) {
        const int i = k >> 5, c = k & 31;
        Wq2[k] = make_float4(W2[i * Hh + c],      W2[i * Hh + c + 32],
                             W2[i * Hh + c + 64], W2[i * Hh + c + 96]);
        Wq3[k] = make_float4(W3[i * Hh + c],      W3[i * Hh + c + 32],
                             W3[i * Hh + c + 64], W3[i * Hh + c + 96]);
    }
    for (int i = tid; i < Hh; i += NTHREADS) {
        w1s[i] = W1[i]; w1s[Hh + i] = W1[Hh + i]; w1s[2 * Hh + i] = W1[2 * Hh + i];
        b1s[i] = b1[i]; b2s[i] = b2[i]; b3s[i] = b3[i]; w4s[i] = W4[i];
    }
    __syncthreads();

    const float nu = nup[0];

    float4* J4 = jets4 + slot * 4 * Hh;
    float2* J2 = jets2 + slot * Hh;

    const int gw = blockIdx.x * SLOTS + slot;     // global warp id
    const int nwarps = gridDim.x * SLOTS;

    for (int n = gw; n < N; n += nwarps) {
        const float px = x[3 * n], py = x[3 * n + 1], pt = x[3 * n + 2];

        float u[NS], o[NS], p[NS];
        u64 acc[36];

        // ---- layer 1 (degree <= 1 pre-activation jets), 4 neurons
#pragma unroll
        for (int t = 0; t < 4; ++t) {
            const int j = jj + 32 * t;
            const float wx = w1s[j], wy = w1s[Hh + j], wt = w1s[2 * Hh + j];
#pragma unroll
            for (int s = 0; s < NS; ++s) u[s] = 0.f;
            u[0] = fmaf(px, wx, fmaf(py, wy, fmaf(pt, wt, b1s[j])));
            u[1] = wx; u[2] = wy; u[3] = wt;
            tanh_jet(u, o);
            store_jets(J4, J2, j, o);
        }
        __syncwarp();

        // ---- layer 2
        matvec4(Wq2, J4, J2, jj, acc);
        __syncwarp();                      // lanes' reads done before overwrite
#pragma unroll
        for (int t = 0; t < 4; ++t) {
            const int j = jj + 32 * t;
#pragma unroll
            for (int s = 0; s < 9; ++s) unpack2(acc[9 * t + s], u[2 * s], u[2 * s + 1]);
            u[0] += b2s[j];
            tanh_jet(u, o);
            store_jets(J4, J2, j, o);
        }
        __syncwarp();

        // ---- layer 3 + layer 4 projection
        matvec4(Wq3, J4, J2, jj, acc);
#pragma unroll
        for (int s = 0; s < NS; ++s) p[s] = 0.f;
#pragma unroll
        for (int t = 0; t < 4; ++t) {
            const int j = jj + 32 * t;
#pragma unroll
            for (int s = 0; s < 9; ++s) unpack2(acc[9 * t + s], u[2 * s], u[2 * s + 1]);
            u[0] += b3s[j];
            tanh_jet(u, o);
            const float wj = w4s[j];
#pragma unroll
            for (int s = 0; s < NS; ++s) p[s] = fmaf(o[s], wj, p[s]);
        }

        // ---- warp-wide reduction of the 18 psi-jet streams
#pragma unroll
        for (int s = 0; s < NS; ++s) {
            float v = p[s];
            v += __shfl_xor_sync(0xffffffffu, v, 16);
            v += __shfl_xor_sync(0xffffffffu, v, 8);
            v += __shfl_xor_sync(0xffffffffu, v, 4);
            v += __shfl_xor_sync(0xffffffffu, v, 2);
            v += __shfl_xor_sync(0xffffffffu, v, 1);
            p[s] = v;
        }

        if (jj == 0) {
            const float uu = p[2];                           // psi_y
            const float vv = -p[1];                          // -psi_x
            const float wx = -(6.f * p[9]  + 2.f * p[11]);   // -(psi_xxx + psi_xyy)
            const float wy = -(2.f * p[10] + 6.f * p[12]);   // -(psi_xxy + psi_yyy)
            const float wt = -(2.f * p[13] + 2.f * p[14]);   // -(psi_xxt + psi_yyt)
            const float lapw = -(24.f * p[15] + 8.f * p[16] + 24.f * p[17]);
            const float nse = wt + wx * uu + wy * vv - nu * lapw;

            out[2 * n]     = uu;
            out[2 * n + 1] = vv;
            out[2 * N + n] = nse;
        }
        __syncwarp();   // jets rewritten next iteration
    }
}

extern "C" void kernel_launch(void* const* d_in, const int* in_sizes, int n_in,
                              void* d_out, int out_size)
{
    const float* x  = (const float*)d_in[0];
    const float* W1 = (const float*)d_in[1];
    const float* b1 = (const float*)d_in[2];
    const float* W2 = (const float*)d_in[3];
    const float* b2 = (const float*)d_in[4];
    const float* W3 = (const float*)d_in[5];
    const float* b3 = (const float*)d_in[6];
    const float* W4 = (const float*)d_in[7];
    const float* b4 = (const float*)d_in[8];
    const float* nu = (const float*)d_in[9];

    const int N = in_sizes[0] / 3;

    // weights 128KB + jets SLOTS*(4*Hh*16 + Hh*8) + vecs 7*Hh*4
    const size_t smem = (size_t)(2 * Hh * 32) * sizeof(float4)
                      + (size_t)SLOTS * (4 * Hh * sizeof(float4) + Hh * sizeof(float2))
                      + 7 * Hh * sizeof(float);
    cudaFuncSetAttribute(hydro_kernel, cudaFuncAttributeMaxDynamicSharedMemorySize,
                         (int)smem);

    int dev = 0, sms = 148;
    cudaGetDevice(&dev);
    cudaDeviceGetAttribute(&sms, cudaDevAttrMultiProcessorCount, dev);

    hydro_kernel<<<sms, NTHREADS, smem>>>(x, W1, b1, W2, b2, W3, b3, W4, b4, nu,
                                          (float*)d_out, N);
}